// round 1
// baseline (speedup 1.0000x reference)
#include <cuda_runtime.h>
#include <cfloat>
#include <math.h>

// ---------------- problem constants ----------------
static constexpr int kNH   = 16;
static constexpr int kS    = 512;
static constexpr int kH    = 2048;
static constexpr int kD    = 128;
static constexpr int kSC   = 8192;   // cache length
static constexpr int kTopK = 16;
static constexpr int kQKVld = 3 * kH;          // 6144
static constexpr float kScale = 0.08838834764831845f;  // 1/sqrt(128)
static constexpr float kSimTh = 0.25f;
static constexpr float kNeg   = -1e30f;

// ---------------- scratch (__device__ globals; no allocation allowed) ----------------
__device__ __align__(16) float g_qkv[kS * kQKVld];                    // 12.6 MB
__device__ __align__(16) float g_sim[(size_t)kNH * kS * kSC];         // 268 MB
__device__ float g_invq[kNH * kS];
__device__ float g_invk[kNH * kSC];
__device__ float g_topv[kNH * kS * kTopK];
__device__ int   g_topi[kNH * kS * kTopK];
__device__ __align__(16) float g_ctx[kS * kH];                        // 4 MB

// ---------------- generic NT SGEMM: C[z] = A[z] (MxK) * B[z] (NxK)^T ----------------
// tile 128x128x16, 256 threads, 8x8 per thread. M,N multiples of 128, K multiple of 16.
// optional epilogue scaling: C *= rowScale[z*rs+row] * colScale[z*cs+col]
__global__ void __launch_bounds__(256, 2)
sgemm_nt(const float* __restrict__ A, int lda, long long aStride,
         const float* __restrict__ B, int ldb, long long bStride,
         float* __restrict__ C, int ldc, long long cStride,
         int K,
         const float* __restrict__ rowScale, int rsStride,
         const float* __restrict__ colScale, int csStride)
{
    __shared__ float As[16][128];
    __shared__ float Bs[16][128];

    const int tid = threadIdx.x;
    const int m0  = blockIdx.y * 128;
    const int n0  = blockIdx.x * 128;
    const int z   = blockIdx.z;

    const float* Ab = A + (long long)z * aStride;
    const float* Bb = B + (long long)z * bStride;

    const int lr = tid >> 2;          // 0..63 (load row)
    const int lc = (tid & 3) << 2;    // 0,4,8,12 (load k-col base)
    const int tx = tid & 15;
    const int ty = tid >> 4;

    float acc[8][8];
#pragma unroll
    for (int i = 0; i < 8; i++)
#pragma unroll
        for (int j = 0; j < 8; j++) acc[i][j] = 0.f;

    for (int k0 = 0; k0 < K; k0 += 16) {
        float4 a0 = *(const float4*)(Ab + (long long)(m0 + lr)      * lda + k0 + lc);
        float4 a1 = *(const float4*)(Ab + (long long)(m0 + lr + 64) * lda + k0 + lc);
        float4 b0 = *(const float4*)(Bb + (long long)(n0 + lr)      * ldb + k0 + lc);
        float4 b1 = *(const float4*)(Bb + (long long)(n0 + lr + 64) * ldb + k0 + lc);
        __syncthreads();
        As[lc + 0][lr] = a0.x; As[lc + 1][lr] = a0.y; As[lc + 2][lr] = a0.z; As[lc + 3][lr] = a0.w;
        As[lc + 0][lr + 64] = a1.x; As[lc + 1][lr + 64] = a1.y; As[lc + 2][lr + 64] = a1.z; As[lc + 3][lr + 64] = a1.w;
        Bs[lc + 0][lr] = b0.x; Bs[lc + 1][lr] = b0.y; Bs[lc + 2][lr] = b0.z; Bs[lc + 3][lr] = b0.w;
        Bs[lc + 0][lr + 64] = b1.x; Bs[lc + 1][lr + 64] = b1.y; Bs[lc + 2][lr + 64] = b1.z; Bs[lc + 3][lr + 64] = b1.w;
        __syncthreads();
#pragma unroll
        for (int kk = 0; kk < 16; kk++) {
            float4 av0 = *(const float4*)&As[kk][ty * 8];
            float4 av1 = *(const float4*)&As[kk][ty * 8 + 4];
            float4 bv0 = *(const float4*)&Bs[kk][tx * 8];
            float4 bv1 = *(const float4*)&Bs[kk][tx * 8 + 4];
            float a[8] = {av0.x, av0.y, av0.z, av0.w, av1.x, av1.y, av1.z, av1.w};
            float b[8] = {bv0.x, bv0.y, bv0.z, bv0.w, bv1.x, bv1.y, bv1.z, bv1.w};
#pragma unroll
            for (int i = 0; i < 8; i++)
#pragma unroll
                for (int j = 0; j < 8; j++) acc[i][j] = fmaf(a[i], b[j], acc[i][j]);
        }
    }

    float* Cb = C + (long long)z * cStride;
    float cs[8];
    if (rowScale) {
#pragma unroll
        for (int j = 0; j < 8; j++) cs[j] = colScale[(long long)z * csStride + n0 + tx * 8 + j];
    }
#pragma unroll
    for (int i = 0; i < 8; i++) {
        const int r = m0 + ty * 8 + i;
        float rs = rowScale ? rowScale[(long long)z * rsStride + r] : 1.f;
        float* crow = Cb + (long long)r * ldc + n0 + tx * 8;
#pragma unroll
        for (int j = 0; j < 8; j++) {
            float v = acc[i][j];
            if (rowScale) v *= rs * cs[j];
            crow[j] = v;
        }
    }
}

// ---------------- inverse norms ----------------
__global__ void qnorm_kernel()
{
    const int gw   = (blockIdx.x * blockDim.x + threadIdx.x) >> 5;
    const int lane = threadIdx.x & 31;
    if (gw >= kNH * kS) return;
    const int h = gw >> 9;   // /512
    const int q = gw & 511;
    float4 v = *(const float4*)(g_qkv + (long long)q * kQKVld + h * kD + lane * 4);
    float s = v.x * v.x + v.y * v.y + v.z * v.z + v.w * v.w;
#pragma unroll
    for (int o = 16; o > 0; o >>= 1) s += __shfl_down_sync(0xffffffffu, s, o);
    if (lane == 0) g_invq[gw] = rsqrtf(s);
}

__global__ void knorm_kernel(const float* __restrict__ kc)
{
    const int gw   = (blockIdx.x * blockDim.x + threadIdx.x) >> 5;
    const int lane = threadIdx.x & 31;
    if (gw >= kNH * kSC) return;
    float4 v = *(const float4*)(kc + (long long)gw * kD + lane * 4);
    float s = v.x * v.x + v.y * v.y + v.z * v.z + v.w * v.w;
#pragma unroll
    for (int o = 16; o > 0; o >>= 1) s += __shfl_down_sync(0xffffffffu, s, o);
    if (lane == 0) g_invk[gw] = rsqrtf(s);
}

// ---------------- per-(h,q) top-16 over 8192 sims ----------------
// one block per row; values register-cached; 16 rounds of block argmax.
// tie-break: lowest index first (matches jax.lax.top_k).
__global__ void __launch_bounds__(256)
topk_kernel()
{
    const long long row = blockIdx.x;  // h*512 + q
    const float* sim = g_sim + row * kSC;
    const int tid = threadIdx.x;
    const int lane = tid & 31;
    const int w = tid >> 5;

    float v[32];
#pragma unroll
    for (int i = 0; i < 32; i++) v[i] = sim[tid + (i << 8)];

    __shared__ float wv[8];
    __shared__ int   wi[8];
    __shared__ int   bi;

    for (int r = 0; r < 16; r++) {
        float mv = -FLT_MAX; int mi = 0x7fffffff;
#pragma unroll
        for (int i = 0; i < 32; i++) {
            if (v[i] > mv) { mv = v[i]; mi = tid + (i << 8); }
        }
#pragma unroll
        for (int o = 16; o > 0; o >>= 1) {
            float ov = __shfl_down_sync(0xffffffffu, mv, o);
            int   oi = __shfl_down_sync(0xffffffffu, mi, o);
            if (ov > mv || (ov == mv && oi < mi)) { mv = ov; mi = oi; }
        }
        if (lane == 0) { wv[w] = mv; wi[w] = mi; }
        __syncthreads();
        if (tid == 0) {
            float m = wv[0]; int ix = wi[0];
#pragma unroll
            for (int k = 1; k < 8; k++)
                if (wv[k] > m || (wv[k] == m && wi[k] < ix)) { m = wv[k]; ix = wi[k]; }
            bi = ix;
            g_topv[row * 16 + r] = m;
            g_topi[row * 16 + r] = ix;
        }
        __syncthreads();
        const int sel = bi;
        if ((sel & 255) == tid) v[sel >> 8] = -FLT_MAX;
    }
}

// ---------------- fused attention per (h,q) ----------------
// ext scores (16 retrieved slots, sim-threshold masked) + causal local scores
// with position bias; softmax; context accumulation; write ctx as [S, H].
__global__ void __launch_bounds__(256)
attn_kernel(const float* __restrict__ kc, const float* __restrict__ vc,
            const float* __restrict__ bias)
{
    const int q = blockIdx.x;
    const int h = blockIdx.y;
    const int tid = threadIdx.x;
    const int lane = tid & 31;
    const int w = tid >> 5;

    __shared__ float qs[128];
    __shared__ float ssc[16 + kS];     // scores: [16 ext | 512 local]
    __shared__ int   sidx[16];
    __shared__ float redw[8];
    __shared__ float bmax, bsuminv;
    __shared__ float ctx2[128];

    const long long rowhq = (long long)h * kS + q;

    if (tid < 128) qs[tid] = g_qkv[(long long)q * kQKVld + h * kD + tid];
    if (tid < 16)  sidx[tid] = g_topi[rowhq * 16 + tid];
    __syncthreads();

    const float4 qv = *(const float4*)(qs + lane * 4);

    // external (retrieved) scores
    for (int j = w; j < 16; j += 8) {
        float s;
        if (g_topv[rowhq * 16 + j] > kSimTh) {
            const float* kp = kc + ((long long)h * kSC + sidx[j]) * kD;
            float4 kv = *(const float4*)(kp + lane * 4);
            float p = qv.x * kv.x + qv.y * kv.y + qv.z * kv.z + qv.w * kv.w;
#pragma unroll
            for (int o = 16; o > 0; o >>= 1) p += __shfl_down_sync(0xffffffffu, p, o);
            s = p * kScale;
        } else {
            s = kNeg;
        }
        if (lane == 0) ssc[j] = s;
    }

    // local causal scores + position bias
    const float* biasrow = bias + ((long long)h * kS + q) * kS;
    for (int kk = w; kk < kS; kk += 8) {
        float s;
        if (kk <= q) {
            const float* kp = g_qkv + (long long)kk * kQKVld + kH + h * kD;
            float4 kv = *(const float4*)(kp + lane * 4);
            float p = qv.x * kv.x + qv.y * kv.y + qv.z * kv.z + qv.w * kv.w;
#pragma unroll
            for (int o = 16; o > 0; o >>= 1) p += __shfl_down_sync(0xffffffffu, p, o);
            s = p * kScale + biasrow[kk];
        } else {
            s = kNeg;
        }
        if (lane == 0) ssc[16 + kk] = s;
    }
    __syncthreads();

    // softmax over 528 entries
    float m = -FLT_MAX;
    for (int j = tid; j < 16 + kS; j += 256) m = fmaxf(m, ssc[j]);
#pragma unroll
    for (int o = 16; o > 0; o >>= 1) m = fmaxf(m, __shfl_down_sync(0xffffffffu, m, o));
    if (lane == 0) redw[w] = m;
    __syncthreads();
    if (tid == 0) {
        float mm = redw[0];
#pragma unroll
        for (int k = 1; k < 8; k++) mm = fmaxf(mm, redw[k]);
        bmax = mm;
    }
    __syncthreads();
    const float msc = bmax;
    float ss = 0.f;
    for (int j = tid; j < 16 + kS; j += 256) {
        float e = __expf(ssc[j] - msc);
        ssc[j] = e;
        ss += e;
    }
#pragma unroll
    for (int o = 16; o > 0; o >>= 1) ss += __shfl_down_sync(0xffffffffu, ss, o);
    if (lane == 0) redw[w] = ss;
    __syncthreads();
    if (tid == 0) {
        float t = 0.f;
#pragma unroll
        for (int k = 0; k < 8; k++) t += redw[k];
        bsuminv = 1.f / t;
    }
    __syncthreads();

    // context: split keys across two 128-thread groups (each owns dim d)
    const int g = tid >> 7;
    const int d = tid & 127;
    float acc = 0.f;
    for (int j = g; j < 16; j += 2) {
        float p = ssc[j];
        if (p > 0.f) acc += p * vc[((long long)h * kSC + sidx[j]) * kD + d];
    }
    for (int kk = g; kk <= q; kk += 2) {
        acc += ssc[16 + kk] * g_qkv[(long long)kk * kQKVld + 2 * kH + h * kD + d];
    }
    if (g == 1) ctx2[d] = acc;
    __syncthreads();
    if (g == 0) {
        g_ctx[(long long)q * kH + h * kD + d] = (acc + ctx2[d]) * bsuminv;
    }
}

// ---------------- launcher ----------------
extern "C" void kernel_launch(void* const* d_in, const int* in_sizes, int n_in,
                              void* d_out, int out_size)
{
    const float* hidden = (const float*)d_in[0];
    const float* Wqkv   = (const float*)d_in[1];
    const float* Wout   = (const float*)d_in[2];
    const float* kc     = (const float*)d_in[3];
    const float* vc     = (const float*)d_in[4];
    const float* bias   = (const float*)d_in[5];
    float* out = (float*)d_out;

    float *p_qkv, *p_sim, *p_ctx, *p_invq, *p_invk;
    cudaGetSymbolAddress((void**)&p_qkv,  g_qkv);
    cudaGetSymbolAddress((void**)&p_sim,  g_sim);
    cudaGetSymbolAddress((void**)&p_ctx,  g_ctx);
    cudaGetSymbolAddress((void**)&p_invq, g_invq);
    cudaGetSymbolAddress((void**)&p_invk, g_invk);

    // 1. QKV projection: [512,2048] x [6144,2048]^T -> [512,6144]
    sgemm_nt<<<dim3(kQKVld / 128, kS / 128, 1), 256>>>(
        hidden, kH, 0, Wqkv, kH, 0, p_qkv, kQKVld, 0, kH,
        nullptr, 0, nullptr, 0);

    // 2. inverse norms of q and k_cache rows
    qnorm_kernel<<<(kNH * kS * 32) / 256, 256>>>();
    knorm_kernel<<<(kNH * kSC * 32) / 256, 256>>>(kc);

    // 3. batched cosine-sim GEMM: per head [512,128] x [8192,128]^T, scaled by invnorms
    sgemm_nt<<<dim3(kSC / 128, kS / 128, kNH), 256>>>(
        p_qkv, kQKVld, 128,
        kc, kD, (long long)kSC * kD,
        p_sim, kSC, (long long)kS * kSC, kD,
        p_invq, kS, p_invk, kSC);

    // 4. top-16 per (h,q) row
    topk_kernel<<<kNH * kS, 256>>>();

    // 5. fused attention (ext + local causal) -> ctx [512, 2048]
    attn_kernel<<<dim3(kS, kNH), 256>>>(kc, vc, bias);

    // 6. output projection: [512,2048] x [2048,2048]^T -> [512,2048]
    sgemm_nt<<<dim3(kH / 128, kS / 128, 1), 256>>>(
        p_ctx, kH, 0, Wout, kH, 0, out, kH, 0, kH,
        nullptr, 0, nullptr, 0);
}

// round 5
// speedup vs baseline: 1.1957x; 1.1957x over previous
#include <cuda_runtime.h>
#include <cuda_bf16.h>
#include <cfloat>
#include <math.h>
#include <stdint.h>

// ---------------- problem constants ----------------
static constexpr int kNH   = 16;
static constexpr int kS    = 512;
static constexpr int kH    = 2048;
static constexpr int kD    = 128;
static constexpr int kSC   = 8192;   // cache length
static constexpr int kTopK = 16;
static constexpr int kCand = 32;     // approx candidate pool per row
static constexpr int kQKVld = 3 * kH;          // 6144
static constexpr float kScale = 0.08838834764831845f;  // 1/sqrt(128)
static constexpr float kSimTh = 0.25f;
static constexpr float kNeg   = -1e30f;

// ---------------- scratch (__device__ globals; no allocation allowed) ----------------
__device__ __align__(16) float g_qkv[kS * kQKVld];                    // 12.6 MB
__device__ __align__(16) float g_sim[(size_t)kNH * kS * kSC];         // 268 MB (approx sims)
__device__ float g_topv[kNH * kS * kTopK];                            // exact vals
__device__ int   g_topi[kNH * kS * kTopK];                            // exact top-16 idx
__device__ int   g_cand[kNH * kS * kCand];                            // approx top-32 pool
__device__ __align__(16) float g_ctx[kS * kH];                        // 4 MB
__device__ __align__(16) float g_qn_f32[kNH * kS * kD];               // normalized q fp32
__device__ __align__(16) float g_kn_f32[(size_t)kNH * kSC * kD];      // normalized k fp32 (64MB)

// bf16 operands
__device__ __align__(16) __nv_bfloat16 g_hid_h[kS * kH];
__device__ __align__(16) __nv_bfloat16 g_hid_l[kS * kH];
__device__ __align__(16) __nv_bfloat16 g_wqkv_h[kQKVld * kH];
__device__ __align__(16) __nv_bfloat16 g_wqkv_l[kQKVld * kH];
__device__ __align__(16) __nv_bfloat16 g_wout_h[kH * kH];
__device__ __align__(16) __nv_bfloat16 g_wout_l[kH * kH];
__device__ __align__(16) __nv_bfloat16 g_qn_h[kNH * kS * kD];
__device__ __align__(16) __nv_bfloat16 g_kn_h[kNH * kSC * kD];
__device__ __align__(16) __nv_bfloat16 g_ctx_h[kS * kH];
__device__ __align__(16) __nv_bfloat16 g_ctx_l[kS * kH];

// ================= warp-mma helpers (compute_103-safe: sm_80 mma.sync) ==========
__device__ __forceinline__ uint32_t smem_u32(const void* p) {
    uint32_t a;
    asm("{ .reg .u64 t; cvta.to.shared.u64 t, %1; cvt.u32.u64 %0, t; }" : "=r"(a) : "l"(p));
    return a;
}
__device__ __forceinline__ void ldsm_x4(uint32_t* r, uint32_t addr) {
    asm volatile("ldmatrix.sync.aligned.m8n8.x4.shared.b16 {%0,%1,%2,%3}, [%4];"
                 : "=r"(r[0]), "=r"(r[1]), "=r"(r[2]), "=r"(r[3]) : "r"(addr));
}
__device__ __forceinline__ void ldsm_x2(uint32_t* r, uint32_t addr) {
    asm volatile("ldmatrix.sync.aligned.m8n8.x2.shared.b16 {%0,%1}, [%2];"
                 : "=r"(r[0]), "=r"(r[1]) : "r"(addr));
}
__device__ __forceinline__ void mma_bf16(float* d, const uint32_t* a, const uint32_t* b) {
    asm volatile(
        "mma.sync.aligned.m16n8k16.row.col.f32.bf16.bf16.f32 "
        "{%0,%1,%2,%3}, {%4,%5,%6,%7}, {%8,%9}, {%0,%1,%2,%3};"
        : "+f"(d[0]), "+f"(d[1]), "+f"(d[2]), "+f"(d[3])
        : "r"(a[0]), "r"(a[1]), "r"(a[2]), "r"(a[3]), "r"(b[0]), "r"(b[1]));
}

// ================= HMMA NT GEMM (templated #products) =================
// NPROD=3: C = (Ah+Al)*(Bh+Bl)^T dropping Al*Bl (near-fp32)
// NPROD=1: C = Ah*Bh^T (plain bf16)
// A:[z][M,K] rm, B:[z][N,K] rm, K mult of 32. CTA 128x128, 8 warps, warp 64x32.
static constexpr int kRowB   = 80;          // bytes per smem row (conflict-free ldmatrix)
static constexpr int kMatB   = 128 * kRowB; // 10240

template<int NPROD>
__global__ void __launch_bounds__(256, 1)
mma_gemm(const __nv_bfloat16* __restrict__ Ah, const __nv_bfloat16* __restrict__ Al,
         const __nv_bfloat16* __restrict__ Bh, const __nv_bfloat16* __restrict__ Bl,
         float* __restrict__ C,
         int lda, int ldb, int ldc,
         long long aS, long long bS, long long cS, int K)
{
    constexpr int AH = 0;
    constexpr int AL = kMatB;
    constexpr int BH = (NPROD == 3) ? 2 * kMatB : kMatB;
    constexpr int BL = 3 * kMatB;
    constexpr int STAGE = ((NPROD == 3) ? 4 : 2) * kMatB;

    extern __shared__ char smem[];
    const uint32_t sb = smem_u32(smem);
    const int tid  = threadIdx.x;
    const int lane = tid & 31;
    const int warp = tid >> 5;
    const int wy = warp >> 2;          // 0..1
    const int wx = warp & 3;           // 0..3
    const int m0 = blockIdx.y * 128, n0 = blockIdx.x * 128, z = blockIdx.z;

    const __nv_bfloat16* pAh = Ah + (long long)z * aS;
    const __nv_bfloat16* pAl = (NPROD == 3) ? Al + (long long)z * aS : nullptr;
    const __nv_bfloat16* pBh = Bh + (long long)z * bS;
    const __nv_bfloat16* pBl = (NPROD == 3) ? Bl + (long long)z * bS : nullptr;

    float acc[4][4][4];
#pragma unroll
    for (int i = 0; i < 4; i++)
#pragma unroll
        for (int j = 0; j < 4; j++)
#pragma unroll
            for (int e = 0; e < 4; e++) acc[i][j][e] = 0.f;

    const int r0s = tid >> 2, c0s = tid & 3;
    const int r1s = (tid + 256) >> 2, c1s = tid & 3;

    const int nCh = K >> 5;

    auto stageStore = [&](int c) {
        const int k0 = c << 5;
        char* stp = smem + (c & 1) * STAGE;
        {
            const long long ga = (long long)(m0 + r0s) * lda + k0 + c0s * 8;
            const long long gb = (long long)(n0 + r0s) * ldb + k0 + c0s * 8;
            const int so = r0s * kRowB + c0s * 16;
            *(uint4*)(stp + AH + so) = *(const uint4*)(pAh + ga);
            *(uint4*)(stp + BH + so) = *(const uint4*)(pBh + gb);
            if (NPROD == 3) {
                *(uint4*)(stp + AL + so) = *(const uint4*)(pAl + ga);
                *(uint4*)(stp + BL + so) = *(const uint4*)(pBl + gb);
            }
        }
        {
            const long long ga = (long long)(m0 + r1s) * lda + k0 + c1s * 8;
            const long long gb = (long long)(n0 + r1s) * ldb + k0 + c1s * 8;
            const int so = r1s * kRowB + c1s * 16;
            *(uint4*)(stp + AH + so) = *(const uint4*)(pAh + ga);
            *(uint4*)(stp + BH + so) = *(const uint4*)(pBh + gb);
            if (NPROD == 3) {
                *(uint4*)(stp + AL + so) = *(const uint4*)(pAl + ga);
                *(uint4*)(stp + BL + so) = *(const uint4*)(pBl + gb);
            }
        }
    };

    stageStore(0);
    __syncthreads();

    const int laneA_row = (lane & 15);
    const int laneA_cb  = (lane >> 4) * 16;
    const int laneB_row = (lane & 7);
    const int laneB_cb  = ((lane >> 3) & 1) * 16;

    for (int c = 0; c < nCh; c++) {
        if (c + 1 < nCh) stageStore(c + 1);

        const uint32_t stb = sb + (c & 1) * STAGE;
#pragma unroll
        for (int kf = 0; kf < 2; kf++) {
            const int kb = kf * 32;
            uint32_t a_h[4][4], a_l[4][4], b_h[4][2], b_l[4][2];
#pragma unroll
            for (int i = 0; i < 4; i++) {
                const uint32_t ra = stb + (uint32_t)((wy * 64 + i * 16 + laneA_row) * kRowB + kb + laneA_cb);
                ldsm_x4(a_h[i], ra + AH);
                if (NPROD == 3) ldsm_x4(a_l[i], ra + AL);
            }
#pragma unroll
            for (int j = 0; j < 4; j++) {
                const uint32_t rb = stb + (uint32_t)((wx * 32 + j * 8 + laneB_row) * kRowB + kb + laneB_cb);
                ldsm_x2(b_h[j], rb + BH);
                if (NPROD == 3) ldsm_x2(b_l[j], rb + BL);
            }
#pragma unroll
            for (int i = 0; i < 4; i++)
#pragma unroll
                for (int j = 0; j < 4; j++) {
                    mma_bf16(acc[i][j], a_h[i], b_h[j]);
                    if (NPROD == 3) {
                        mma_bf16(acc[i][j], a_h[i], b_l[j]);
                        mma_bf16(acc[i][j], a_l[i], b_h[j]);
                    }
                }
        }
        __syncthreads();
    }

    float* Cb = C + (long long)z * cS;
#pragma unroll
    for (int i = 0; i < 4; i++) {
        const int rr = m0 + wy * 64 + i * 16 + (lane >> 2);
#pragma unroll
        for (int j = 0; j < 4; j++) {
            const int cc = n0 + wx * 32 + j * 8 + (lane & 3) * 2;
            float2 v0; v0.x = acc[i][j][0]; v0.y = acc[i][j][1];
            float2 v1; v1.x = acc[i][j][2]; v1.y = acc[i][j][3];
            *(float2*)(Cb + (long long)rr * ldc + cc)       = v0;
            *(float2*)(Cb + (long long)(rr + 8) * ldc + cc) = v1;
        }
    }
}

// ================= fp32 SGEMM (exact path for Q projection) =================
// C = A (MxK) * B (NxK)^T ; tile 128x128x16, 256 threads, 8x8/thread.
__global__ void __launch_bounds__(256, 2)
sgemm_nt(const float* __restrict__ A, int lda,
         const float* __restrict__ B, int ldb,
         float* __restrict__ C, int ldc, int K)
{
    __shared__ float As[16][128];
    __shared__ float Bs[16][128];

    const int tid = threadIdx.x;
    const int m0  = blockIdx.y * 128;
    const int n0  = blockIdx.x * 128;

    const int lr = tid >> 2;
    const int lc = (tid & 3) << 2;
    const int tx = tid & 15;
    const int ty = tid >> 4;

    float acc[8][8];
#pragma unroll
    for (int i = 0; i < 8; i++)
#pragma unroll
        for (int j = 0; j < 8; j++) acc[i][j] = 0.f;

    for (int k0 = 0; k0 < K; k0 += 16) {
        float4 a0 = *(const float4*)(A + (long long)(m0 + lr)      * lda + k0 + lc);
        float4 a1 = *(const float4*)(A + (long long)(m0 + lr + 64) * lda + k0 + lc);
        float4 b0 = *(const float4*)(B + (long long)(n0 + lr)      * ldb + k0 + lc);
        float4 b1 = *(const float4*)(B + (long long)(n0 + lr + 64) * ldb + k0 + lc);
        __syncthreads();
        As[lc + 0][lr] = a0.x; As[lc + 1][lr] = a0.y; As[lc + 2][lr] = a0.z; As[lc + 3][lr] = a0.w;
        As[lc + 0][lr + 64] = a1.x; As[lc + 1][lr + 64] = a1.y; As[lc + 2][lr + 64] = a1.z; As[lc + 3][lr + 64] = a1.w;
        Bs[lc + 0][lr] = b0.x; Bs[lc + 1][lr] = b0.y; Bs[lc + 2][lr] = b0.z; Bs[lc + 3][lr] = b0.w;
        Bs[lc + 0][lr + 64] = b1.x; Bs[lc + 1][lr + 64] = b1.y; Bs[lc + 2][lr + 64] = b1.z; Bs[lc + 3][lr + 64] = b1.w;
        __syncthreads();
#pragma unroll
        for (int kk = 0; kk < 16; kk++) {
            float4 av0 = *(const float4*)&As[kk][ty * 8];
            float4 av1 = *(const float4*)&As[kk][ty * 8 + 4];
            float4 bv0 = *(const float4*)&Bs[kk][tx * 8];
            float4 bv1 = *(const float4*)&Bs[kk][tx * 8 + 4];
            float a[8] = {av0.x, av0.y, av0.z, av0.w, av1.x, av1.y, av1.z, av1.w};
            float b[8] = {bv0.x, bv0.y, bv0.z, bv0.w, bv1.x, bv1.y, bv1.z, bv1.w};
#pragma unroll
            for (int i = 0; i < 8; i++)
#pragma unroll
                for (int j = 0; j < 8; j++) acc[i][j] = fmaf(a[i], b[j], acc[i][j]);
        }
    }

#pragma unroll
    for (int i = 0; i < 8; i++) {
        float* crow = C + (long long)(m0 + ty * 8 + i) * ldc + n0 + tx * 8;
#pragma unroll
        for (int j = 0; j < 8; j++) crow[j] = acc[i][j];
    }
}

// ================= splits =================
__global__ void split_kernel(const float* __restrict__ src,
                             __nv_bfloat16* __restrict__ hi,
                             __nv_bfloat16* __restrict__ lo, int n4)
{
    const int i = blockIdx.x * blockDim.x + threadIdx.x;
    if (i >= n4) return;
    const float4 v = ((const float4*)src)[i];
    __nv_bfloat16 h0 = __float2bfloat16(v.x);
    __nv_bfloat16 h1 = __float2bfloat16(v.y);
    __nv_bfloat16 h2 = __float2bfloat16(v.z);
    __nv_bfloat16 h3 = __float2bfloat16(v.w);
    __nv_bfloat162 H0; H0.x = h0; H0.y = h1;
    __nv_bfloat162 H1; H1.x = h2; H1.y = h3;
    __nv_bfloat162 L0, L1;
    L0.x = __float2bfloat16(v.x - __bfloat162float(h0));
    L0.y = __float2bfloat16(v.y - __bfloat162float(h1));
    L1.x = __float2bfloat16(v.z - __bfloat162float(h2));
    L1.y = __float2bfloat16(v.w - __bfloat162float(h3));
    ((__nv_bfloat162*)hi)[2 * i]     = H0;
    ((__nv_bfloat162*)hi)[2 * i + 1] = H1;
    ((__nv_bfloat162*)lo)[2 * i]     = L0;
    ((__nv_bfloat162*)lo)[2 * i + 1] = L1;
}

// normalized q rows -> fp32 [h][s][128] + bf16 hi  (one warp per row)
__global__ void qsplit_kernel()
{
    const int gw   = (blockIdx.x * blockDim.x + threadIdx.x) >> 5;
    const int lane = threadIdx.x & 31;
    if (gw >= kNH * kS) return;
    const int h = gw >> 9;
    const int q = gw & 511;
    float4 v = *(const float4*)(g_qkv + (long long)q * kQKVld + h * kD + lane * 4);
    float s = v.x * v.x + v.y * v.y + v.z * v.z + v.w * v.w;
#pragma unroll
    for (int o = 16; o > 0; o >>= 1) s += __shfl_xor_sync(0xffffffffu, s, o);
    const float inv = rsqrtf(s);
    v.x *= inv; v.y *= inv; v.z *= inv; v.w *= inv;
    const long long base = (long long)gw * kD + lane * 4;
    *(float4*)(g_qn_f32 + base) = v;
    __nv_bfloat162 H0, H1;
    H0.x = __float2bfloat16(v.x); H0.y = __float2bfloat16(v.y);
    H1.x = __float2bfloat16(v.z); H1.y = __float2bfloat16(v.w);
    *(__nv_bfloat162*)(g_qn_h + base)     = H0;
    *(__nv_bfloat162*)(g_qn_h + base + 2) = H1;
}

// normalized k_cache rows -> fp32 + bf16 hi  (one warp per row)
__global__ void ksplit_kernel(const float* __restrict__ kc)
{
    const int gw   = (blockIdx.x * blockDim.x + threadIdx.x) >> 5;
    const int lane = threadIdx.x & 31;
    if (gw >= kNH * kSC) return;
    float4 v = *(const float4*)(kc + (long long)gw * kD + lane * 4);
    float s = v.x * v.x + v.y * v.y + v.z * v.z + v.w * v.w;
#pragma unroll
    for (int o = 16; o > 0; o >>= 1) s += __shfl_xor_sync(0xffffffffu, s, o);
    const float inv = rsqrtf(s);
    v.x *= inv; v.y *= inv; v.z *= inv; v.w *= inv;
    const long long base = (long long)gw * kD + lane * 4;
    *(float4*)(g_kn_f32 + base) = v;
    __nv_bfloat162 H0, H1;
    H0.x = __float2bfloat16(v.x); H0.y = __float2bfloat16(v.y);
    H1.x = __float2bfloat16(v.z); H1.y = __float2bfloat16(v.w);
    *(__nv_bfloat162*)(g_kn_h + base)     = H0;
    *(__nv_bfloat162*)(g_kn_h + base + 2) = H1;
}

// ---------------- per-(h,q) approx top-32 over 8192 sims ----------------
__global__ void __launch_bounds__(256)
topk_kernel()
{
    const long long row = blockIdx.x;  // h*512 + q
    const float* sim = g_sim + row * kSC;
    const int tid = threadIdx.x;
    const int lane = tid & 31;
    const int w = tid >> 5;

    float v[32];
#pragma unroll
    for (int i = 0; i < 32; i++) v[i] = sim[tid + (i << 8)];

    __shared__ float wv[8];
    __shared__ int   wi[8];
    __shared__ int   bi;

    for (int r = 0; r < kCand; r++) {
        float mv = -FLT_MAX; int mi = 0x7fffffff;
#pragma unroll
        for (int i = 0; i < 32; i++) {
            if (v[i] > mv) { mv = v[i]; mi = tid + (i << 8); }
        }
#pragma unroll
        for (int o = 16; o > 0; o >>= 1) {
            float ov = __shfl_down_sync(0xffffffffu, mv, o);
            int   oi = __shfl_down_sync(0xffffffffu, mi, o);
            if (ov > mv || (ov == mv && oi < mi)) { mv = ov; mi = oi; }
        }
        if (lane == 0) { wv[w] = mv; wi[w] = mi; }
        __syncthreads();
        if (tid == 0) {
            float m = wv[0]; int ix = wi[0];
#pragma unroll
            for (int k = 1; k < 8; k++)
                if (wv[k] > m || (wv[k] == m && wi[k] < ix)) { m = wv[k]; ix = wi[k]; }
            bi = ix;
            g_cand[row * kCand + r] = ix;
        }
        __syncthreads();
        const int sel = bi;
        if ((sel & 255) == tid) v[sel >> 8] = -FLT_MAX;
    }
}

// ---------------- exact rescore of 32 candidates -> exact top-16 ----------------
// one warp per (h,q) row; normalize-then-dot in fp32 matching reference op order.
__global__ void __launch_bounds__(256)
rescore_kernel()
{
    const int gw   = (blockIdx.x * blockDim.x + threadIdx.x) >> 5;
    const int lane = threadIdx.x & 31;
    if (gw >= kNH * kS) return;
    const int h = gw >> 9;

    const float4 qv = *(const float4*)(g_qn_f32 + (long long)gw * kD + lane * 4);
    int   myidx = g_cand[gw * kCand + lane];
    float myval = -FLT_MAX;

    for (int c = 0; c < kCand; c++) {
        const int idx = __shfl_sync(0xffffffffu, myidx, c);
        const float4 kv = *(const float4*)(g_kn_f32 + ((long long)h * kSC + idx) * kD + lane * 4);
        float p = qv.x * kv.x + qv.y * kv.y + qv.z * kv.z + qv.w * kv.w;
#pragma unroll
        for (int o = 16; o > 0; o >>= 1) p += __shfl_xor_sync(0xffffffffu, p, o);
        if (lane == c) myval = p;
    }

    for (int r = 0; r < kTopK; r++) {
        float v = myval; int ix = myidx;
#pragma unroll
        for (int o = 16; o > 0; o >>= 1) {
            float ov = __shfl_xor_sync(0xffffffffu, v, o);
            int   oi = __shfl_xor_sync(0xffffffffu, ix, o);
            if (ov > v || (ov == v && oi < ix)) { v = ov; ix = oi; }
        }
        if (lane == 0) {
            g_topv[gw * kTopK + r] = v;
            g_topi[gw * kTopK + r] = ix;
        }
        if (myidx == ix) myval = -FLT_MAX;
    }
}

// ---------------- fused attention per (h,q) ----------------
__global__ void __launch_bounds__(256)
attn_kernel(const float* __restrict__ kc, const float* __restrict__ vc,
            const float* __restrict__ bias)
{
    const int q = blockIdx.x;
    const int h = blockIdx.y;
    const int tid = threadIdx.x;
    const int lane = tid & 31;
    const int w = tid >> 5;

    __shared__ float qs[128];
    __shared__ float ssc[16 + kS];
    __shared__ int   sidx[16];
    __shared__ float redw[8];
    __shared__ float bmax, bsuminv;
    __shared__ float ctx2[128];

    const long long rowhq = (long long)h * kS + q;

    if (tid < 128) qs[tid] = g_qkv[(long long)q * kQKVld + h * kD + tid];
    if (tid < 16)  sidx[tid] = g_topi[rowhq * 16 + tid];
    __syncthreads();

    const float4 qv = *(const float4*)(qs + lane * 4);

    for (int j = w; j < 16; j += 8) {
        float s;
        if (g_topv[rowhq * 16 + j] > kSimTh) {
            const float* kp = kc + ((long long)h * kSC + sidx[j]) * kD;
            float4 kv = *(const float4*)(kp + lane * 4);
            float p = qv.x * kv.x + qv.y * kv.y + qv.z * kv.z + qv.w * kv.w;
#pragma unroll
            for (int o = 16; o > 0; o >>= 1) p += __shfl_down_sync(0xffffffffu, p, o);
            s = p * kScale;
        } else {
            s = kNeg;
        }
        if (lane == 0) ssc[j] = s;
    }

    const float* biasrow = bias + ((long long)h * kS + q) * kS;
    for (int kk = w; kk < kS; kk += 8) {
        float s;
        if (kk <= q) {
            const float* kp = g_qkv + (long long)kk * kQKVld + kH + h * kD;
            float4 kv = *(const float4*)(kp + lane * 4);
            float p = qv.x * kv.x + qv.y * kv.y + qv.z * kv.z + qv.w * kv.w;
#pragma unroll
            for (int o = 16; o > 0; o >>= 1) p += __shfl_down_sync(0xffffffffu, p, o);
            s = p * kScale + biasrow[kk];
        } else {
            s = kNeg;
        }
        if (lane == 0) ssc[16 + kk] = s;
    }
    __syncthreads();

    float m = -FLT_MAX;
    for (int j = tid; j < 16 + kS; j += 256) m = fmaxf(m, ssc[j]);
#pragma unroll
    for (int o = 16; o > 0; o >>= 1) m = fmaxf(m, __shfl_down_sync(0xffffffffu, m, o));
    if (lane == 0) redw[w] = m;
    __syncthreads();
    if (tid == 0) {
        float mm = redw[0];
#pragma unroll
        for (int k = 1; k < 8; k++) mm = fmaxf(mm, redw[k]);
        bmax = mm;
    }
    __syncthreads();
    const float msc = bmax;
    float ss = 0.f;
    for (int j = tid; j < 16 + kS; j += 256) {
        float e = __expf(ssc[j] - msc);
        ssc[j] = e;
        ss += e;
    }
#pragma unroll
    for (int o = 16; o > 0; o >>= 1) ss += __shfl_down_sync(0xffffffffu, ss, o);
    if (lane == 0) redw[w] = ss;
    __syncthreads();
    if (tid == 0) {
        float t = 0.f;
#pragma unroll
        for (int k = 0; k < 8; k++) t += redw[k];
        bsuminv = 1.f / t;
    }
    __syncthreads();

    const int g = tid >> 7;
    const int d = tid & 127;
    float acc = 0.f;
    for (int j = g; j < 16; j += 2) {
        float p = ssc[j];
        if (p > 0.f) acc += p * vc[((long long)h * kSC + sidx[j]) * kD + d];
    }
    for (int kk = g; kk <= q; kk += 2) {
        acc += ssc[16 + kk] * g_qkv[(long long)kk * kQKVld + 2 * kH + h * kD + d];
    }
    if (g == 1) ctx2[d] = acc;
    __syncthreads();
    if (g == 0) {
        g_ctx[(long long)q * kH + h * kD + d] = (acc + ctx2[d]) * bsuminv;
    }
}

// ---------------- launcher ----------------
extern "C" void kernel_launch(void* const* d_in, const int* in_sizes, int n_in,
                              void* d_out, int out_size)
{
    const float* hidden = (const float*)d_in[0];
    const float* Wqkv   = (const float*)d_in[1];
    const float* Wout   = (const float*)d_in[2];
    const float* kc     = (const float*)d_in[3];
    const float* vc     = (const float*)d_in[4];
    const float* bias   = (const float*)d_in[5];
    float* out = (float*)d_out;

    float *p_qkv, *p_sim, *p_ctx;
    cudaGetSymbolAddress((void**)&p_qkv,  g_qkv);
    cudaGetSymbolAddress((void**)&p_sim,  g_sim);
    cudaGetSymbolAddress((void**)&p_ctx,  g_ctx);
    __nv_bfloat16 *p_hid_h, *p_hid_l, *p_wqkv_h, *p_wqkv_l, *p_wout_h, *p_wout_l;
    __nv_bfloat16 *p_qn_h, *p_kn_h, *p_ctx_h, *p_ctx_l;
    cudaGetSymbolAddress((void**)&p_hid_h,  g_hid_h);
    cudaGetSymbolAddress((void**)&p_hid_l,  g_hid_l);
    cudaGetSymbolAddress((void**)&p_wqkv_h, g_wqkv_h);
    cudaGetSymbolAddress((void**)&p_wqkv_l, g_wqkv_l);
    cudaGetSymbolAddress((void**)&p_wout_h, g_wout_h);
    cudaGetSymbolAddress((void**)&p_wout_l, g_wout_l);
    cudaGetSymbolAddress((void**)&p_qn_h,   g_qn_h);
    cudaGetSymbolAddress((void**)&p_kn_h,   g_kn_h);
    cudaGetSymbolAddress((void**)&p_ctx_h,  g_ctx_h);
    cudaGetSymbolAddress((void**)&p_ctx_l,  g_ctx_l);

    cudaFuncSetAttribute(mma_gemm<3>, cudaFuncAttributeMaxDynamicSharedMemorySize, 2 * 4 * kMatB);
    cudaFuncSetAttribute(mma_gemm<1>, cudaFuncAttributeMaxDynamicSharedMemorySize, 2 * 2 * kMatB);

    // 1. splits of weights / hidden + normalized k cache (fp32 + bf16)
    split_kernel<<<(kQKVld * kH / 4 + 255) / 256, 256>>>(Wqkv, p_wqkv_h, p_wqkv_l, kQKVld * kH / 4);
    split_kernel<<<(kH * kH / 4 + 255) / 256, 256>>>(Wout, p_wout_h, p_wout_l, kH * kH / 4);
    split_kernel<<<(kS * kH / 4 + 255) / 256, 256>>>(hidden, p_hid_h, p_hid_l, kS * kH / 4);
    ksplit_kernel<<<(kNH * kSC * 32) / 256, 256>>>(kc);

    // 2a. Q projection EXACT fp32: [512,2048] x [2048,2048]^T -> g_qkv cols [0,2048)
    sgemm_nt<<<dim3(kH / 128, kS / 128), 256>>>(hidden, kH, Wqkv, kH, p_qkv, kQKVld, kH);

    // 2b. K,V projections (HMMA 3-prod): [512,2048] x [4096,2048]^T -> g_qkv cols [2048,6144)
    mma_gemm<3><<<dim3(4096 / 128, kS / 128, 1), 256, 2 * 4 * kMatB>>>(
        p_hid_h, p_hid_l, p_wqkv_h + (size_t)2048 * kH, p_wqkv_l + (size_t)2048 * kH,
        p_qkv + 2048, kH, kH, kQKVld, 0, 0, 0, kH);

    // 3. normalized q (fp32 + bf16)
    qsplit_kernel<<<(kNH * kS * 32) / 256, 256>>>();

    // 4. approx cosine-sim GEMM (HMMA 1-prod bf16): per head [512,128]x[8192,128]^T
    mma_gemm<1><<<dim3(kSC / 128, kS / 128, kNH), 256, 2 * 2 * kMatB>>>(
        p_qn_h, nullptr, p_kn_h, nullptr, p_sim,
        kD, kD, kSC,
        (long long)kS * kD, (long long)kSC * kD, (long long)kS * kSC, kD);

    // 5. approx top-32 candidate pool per (h,q)
    topk_kernel<<<kNH * kS, 256>>>();

    // 6. exact fp32 rescore -> exact top-16 values + indices
    rescore_kernel<<<(kNH * kS * 32 + 255) / 256, 256>>>();

    // 7. fused attention -> g_ctx [512, 2048]
    attn_kernel<<<dim3(kS, kNH), 256>>>(kc, vc, bias);

    // 8. ctx split + output projection (HMMA 3-prod)
    split_kernel<<<(kS * kH / 4 + 255) / 256, 256>>>(p_ctx, p_ctx_h, p_ctx_l, kS * kH / 4);
    mma_gemm<3><<<dim3(kH / 128, kS / 128, 1), 256, 2 * 4 * kMatB>>>(
        p_ctx_h, p_ctx_l, p_wout_h, p_wout_l, out,
        kH, kH, kH, 0, 0, 0, kH);
}

// round 6
// speedup vs baseline: 1.1970x; 1.0011x over previous
#include <cuda_runtime.h>
#include <cuda_bf16.h>
#include <cfloat>
#include <math.h>
#include <stdint.h>

// ---------------- problem constants ----------------
static constexpr int kNH   = 16;
static constexpr int kS    = 512;
static constexpr int kH    = 2048;
static constexpr int kD    = 128;
static constexpr int kSC   = 8192;   // cache length
static constexpr int kTopK = 16;
static constexpr int kCand = 32;     // approx candidate pool per row
static constexpr int kQKVld = 3 * kH;          // 6144
static constexpr float kScale = 0.08838834764831845f;  // 1/sqrt(128)
static constexpr float kSimTh = 0.25f;
static constexpr float kNeg   = -1e30f;

// ---------------- scratch (__device__ globals; no allocation allowed) ----------------
__device__ __align__(16) float g_qkv[kS * kQKVld];                    // 12.6 MB
__device__ __align__(16) float g_sim[(size_t)kNH * kS * kSC];         // 268 MB (approx sims)
__device__ float g_topv[kNH * kS * kTopK];                            // exact vals
__device__ int   g_topi[kNH * kS * kTopK];                            // exact top-16 idx
__device__ int   g_cand[kNH * kS * kCand];                            // approx top-32 pool
__device__ __align__(16) float g_ctx[kS * kH];                        // 4 MB
__device__ __align__(16) float g_qn_f32[kNH * kS * kD];               // normalized q fp32
__device__ __align__(16) float g_kn_f32[(size_t)kNH * kSC * kD];      // normalized k fp32 (64MB)

// bf16 operands
__device__ __align__(16) __nv_bfloat16 g_hid_h[kS * kH];
__device__ __align__(16) __nv_bfloat16 g_hid_l[kS * kH];
__device__ __align__(16) __nv_bfloat16 g_wqkv_h[kQKVld * kH];
__device__ __align__(16) __nv_bfloat16 g_wqkv_l[kQKVld * kH];
__device__ __align__(16) __nv_bfloat16 g_wout_h[kH * kH];
__device__ __align__(16) __nv_bfloat16 g_wout_l[kH * kH];
__device__ __align__(16) __nv_bfloat16 g_qn_h[kNH * kS * kD];
__device__ __align__(16) __nv_bfloat16 g_kn_h[kNH * kSC * kD];
__device__ __align__(16) __nv_bfloat16 g_ctx_h[kS * kH];
__device__ __align__(16) __nv_bfloat16 g_ctx_l[kS * kH];

// ================= warp-mma helpers (compute_103-safe: sm_80 mma.sync) ==========
__device__ __forceinline__ uint32_t smem_u32(const void* p) {
    uint32_t a;
    asm("{ .reg .u64 t; cvta.to.shared.u64 t, %1; cvt.u32.u64 %0, t; }" : "=r"(a) : "l"(p));
    return a;
}
__device__ __forceinline__ void ldsm_x4(uint32_t* r, uint32_t addr) {
    asm volatile("ldmatrix.sync.aligned.m8n8.x4.shared.b16 {%0,%1,%2,%3}, [%4];"
                 : "=r"(r[0]), "=r"(r[1]), "=r"(r[2]), "=r"(r[3]) : "r"(addr));
}
__device__ __forceinline__ void ldsm_x2(uint32_t* r, uint32_t addr) {
    asm volatile("ldmatrix.sync.aligned.m8n8.x2.shared.b16 {%0,%1}, [%2];"
                 : "=r"(r[0]), "=r"(r[1]) : "r"(addr));
}
__device__ __forceinline__ void mma_bf16(float* d, const uint32_t* a, const uint32_t* b) {
    asm volatile(
        "mma.sync.aligned.m16n8k16.row.col.f32.bf16.bf16.f32 "
        "{%0,%1,%2,%3}, {%4,%5,%6,%7}, {%8,%9}, {%0,%1,%2,%3};"
        : "+f"(d[0]), "+f"(d[1]), "+f"(d[2]), "+f"(d[3])
        : "r"(a[0]), "r"(a[1]), "r"(a[2]), "r"(a[3]), "r"(b[0]), "r"(b[1]));
}

// ================= HMMA NT GEMM (templated #products) =================
// NPROD=3: C = (Ah+Al)*(Bh+Bl)^T dropping Al*Bl (near-fp32)
// NPROD=1: C = Ah*Bh^T (plain bf16)
// A:[z][M,K] rm, B:[z][N,K] rm, K mult of 32. CTA 128x128, 8 warps, warp 64x32.
static constexpr int kRowB   = 80;          // bytes per smem row (conflict-free ldmatrix)
static constexpr int kMatB   = 128 * kRowB; // 10240

template<int NPROD>
__global__ void __launch_bounds__(256, 1)
mma_gemm(const __nv_bfloat16* __restrict__ Ah, const __nv_bfloat16* __restrict__ Al,
         const __nv_bfloat16* __restrict__ Bh, const __nv_bfloat16* __restrict__ Bl,
         float* __restrict__ C,
         int lda, int ldb, int ldc,
         long long aS, long long bS, long long cS, int K)
{
    constexpr int AH = 0;
    constexpr int AL = kMatB;
    constexpr int BH = (NPROD == 3) ? 2 * kMatB : kMatB;
    constexpr int BL = 3 * kMatB;
    constexpr int STAGE = ((NPROD == 3) ? 4 : 2) * kMatB;

    extern __shared__ char smem[];
    const uint32_t sb = smem_u32(smem);
    const int tid  = threadIdx.x;
    const int lane = tid & 31;
    const int warp = tid >> 5;
    const int wy = warp >> 2;          // 0..1
    const int wx = warp & 3;           // 0..3
    const int m0 = blockIdx.y * 128, n0 = blockIdx.x * 128, z = blockIdx.z;

    const __nv_bfloat16* pAh = Ah + (long long)z * aS;
    const __nv_bfloat16* pAl = (NPROD == 3) ? Al + (long long)z * aS : nullptr;
    const __nv_bfloat16* pBh = Bh + (long long)z * bS;
    const __nv_bfloat16* pBl = (NPROD == 3) ? Bl + (long long)z * bS : nullptr;

    float acc[4][4][4];
#pragma unroll
    for (int i = 0; i < 4; i++)
#pragma unroll
        for (int j = 0; j < 4; j++)
#pragma unroll
            for (int e = 0; e < 4; e++) acc[i][j][e] = 0.f;

    const int r0s = tid >> 2, c0s = tid & 3;
    const int r1s = (tid + 256) >> 2, c1s = tid & 3;

    const int nCh = K >> 5;

    auto stageStore = [&](int c) {
        const int k0 = c << 5;
        char* stp = smem + (c & 1) * STAGE;
        {
            const long long ga = (long long)(m0 + r0s) * lda + k0 + c0s * 8;
            const long long gb = (long long)(n0 + r0s) * ldb + k0 + c0s * 8;
            const int so = r0s * kRowB + c0s * 16;
            *(uint4*)(stp + AH + so) = *(const uint4*)(pAh + ga);
            *(uint4*)(stp + BH + so) = *(const uint4*)(pBh + gb);
            if (NPROD == 3) {
                *(uint4*)(stp + AL + so) = *(const uint4*)(pAl + ga);
                *(uint4*)(stp + BL + so) = *(const uint4*)(pBl + gb);
            }
        }
        {
            const long long ga = (long long)(m0 + r1s) * lda + k0 + c1s * 8;
            const long long gb = (long long)(n0 + r1s) * ldb + k0 + c1s * 8;
            const int so = r1s * kRowB + c1s * 16;
            *(uint4*)(stp + AH + so) = *(const uint4*)(pAh + ga);
            *(uint4*)(stp + BH + so) = *(const uint4*)(pBh + gb);
            if (NPROD == 3) {
                *(uint4*)(stp + AL + so) = *(const uint4*)(pAl + ga);
                *(uint4*)(stp + BL + so) = *(const uint4*)(pBl + gb);
            }
        }
    };

    stageStore(0);
    __syncthreads();

    const int laneA_row = (lane & 15);
    const int laneA_cb  = (lane >> 4) * 16;
    const int laneB_row = (lane & 7);
    const int laneB_cb  = ((lane >> 3) & 1) * 16;

    for (int c = 0; c < nCh; c++) {
        if (c + 1 < nCh) stageStore(c + 1);

        const uint32_t stb = sb + (c & 1) * STAGE;
#pragma unroll
        for (int kf = 0; kf < 2; kf++) {
            const int kb = kf * 32;
            uint32_t a_h[4][4], a_l[4][4], b_h[4][2], b_l[4][2];
#pragma unroll
            for (int i = 0; i < 4; i++) {
                const uint32_t ra = stb + (uint32_t)((wy * 64 + i * 16 + laneA_row) * kRowB + kb + laneA_cb);
                ldsm_x4(a_h[i], ra + AH);
                if (NPROD == 3) ldsm_x4(a_l[i], ra + AL);
            }
#pragma unroll
            for (int j = 0; j < 4; j++) {
                const uint32_t rb = stb + (uint32_t)((wx * 32 + j * 8 + laneB_row) * kRowB + kb + laneB_cb);
                ldsm_x2(b_h[j], rb + BH);
                if (NPROD == 3) ldsm_x2(b_l[j], rb + BL);
            }
#pragma unroll
            for (int i = 0; i < 4; i++)
#pragma unroll
                for (int j = 0; j < 4; j++) {
                    mma_bf16(acc[i][j], a_h[i], b_h[j]);
                    if (NPROD == 3) {
                        mma_bf16(acc[i][j], a_h[i], b_l[j]);
                        mma_bf16(acc[i][j], a_l[i], b_h[j]);
                    }
                }
        }
        __syncthreads();
    }

    float* Cb = C + (long long)z * cS;
#pragma unroll
    for (int i = 0; i < 4; i++) {
        const int rr = m0 + wy * 64 + i * 16 + (lane >> 2);
#pragma unroll
        for (int j = 0; j < 4; j++) {
            const int cc = n0 + wx * 32 + j * 8 + (lane & 3) * 2;
            float2 v0; v0.x = acc[i][j][0]; v0.y = acc[i][j][1];
            float2 v1; v1.x = acc[i][j][2]; v1.y = acc[i][j][3];
            *(float2*)(Cb + (long long)rr * ldc + cc)       = v0;
            *(float2*)(Cb + (long long)(rr + 8) * ldc + cc) = v1;
        }
    }
}

// ================= fp32 SGEMM (exact path for Q projection) =================
// C = A (MxK) * B (NxK)^T ; tile 128x128x16, 256 threads, 8x8/thread.
__global__ void __launch_bounds__(256, 2)
sgemm_nt(const float* __restrict__ A, int lda,
         const float* __restrict__ B, int ldb,
         float* __restrict__ C, int ldc, int K)
{
    __shared__ float As[16][128];
    __shared__ float Bs[16][128];

    const int tid = threadIdx.x;
    const int m0  = blockIdx.y * 128;
    const int n0  = blockIdx.x * 128;

    const int lr = tid >> 2;
    const int lc = (tid & 3) << 2;
    const int tx = tid & 15;
    const int ty = tid >> 4;

    float acc[8][8];
#pragma unroll
    for (int i = 0; i < 8; i++)
#pragma unroll
        for (int j = 0; j < 8; j++) acc[i][j] = 0.f;

    for (int k0 = 0; k0 < K; k0 += 16) {
        float4 a0 = *(const float4*)(A + (long long)(m0 + lr)      * lda + k0 + lc);
        float4 a1 = *(const float4*)(A + (long long)(m0 + lr + 64) * lda + k0 + lc);
        float4 b0 = *(const float4*)(B + (long long)(n0 + lr)      * ldb + k0 + lc);
        float4 b1 = *(const float4*)(B + (long long)(n0 + lr + 64) * ldb + k0 + lc);
        __syncthreads();
        As[lc + 0][lr] = a0.x; As[lc + 1][lr] = a0.y; As[lc + 2][lr] = a0.z; As[lc + 3][lr] = a0.w;
        As[lc + 0][lr + 64] = a1.x; As[lc + 1][lr + 64] = a1.y; As[lc + 2][lr + 64] = a1.z; As[lc + 3][lr + 64] = a1.w;
        Bs[lc + 0][lr] = b0.x; Bs[lc + 1][lr] = b0.y; Bs[lc + 2][lr] = b0.z; Bs[lc + 3][lr] = b0.w;
        Bs[lc + 0][lr + 64] = b1.x; Bs[lc + 1][lr + 64] = b1.y; Bs[lc + 2][lr + 64] = b1.z; Bs[lc + 3][lr + 64] = b1.w;
        __syncthreads();
#pragma unroll
        for (int kk = 0; kk < 16; kk++) {
            float4 av0 = *(const float4*)&As[kk][ty * 8];
            float4 av1 = *(const float4*)&As[kk][ty * 8 + 4];
            float4 bv0 = *(const float4*)&Bs[kk][tx * 8];
            float4 bv1 = *(const float4*)&Bs[kk][tx * 8 + 4];
            float a[8] = {av0.x, av0.y, av0.z, av0.w, av1.x, av1.y, av1.z, av1.w};
            float b[8] = {bv0.x, bv0.y, bv0.z, bv0.w, bv1.x, bv1.y, bv1.z, bv1.w};
#pragma unroll
            for (int i = 0; i < 8; i++)
#pragma unroll
                for (int j = 0; j < 8; j++) acc[i][j] = fmaf(a[i], b[j], acc[i][j]);
        }
    }

#pragma unroll
    for (int i = 0; i < 8; i++) {
        float* crow = C + (long long)(m0 + ty * 8 + i) * ldc + n0 + tx * 8;
#pragma unroll
        for (int j = 0; j < 8; j++) crow[j] = acc[i][j];
    }
}

// ================= splits =================
__global__ void split_kernel(const float* __restrict__ src,
                             __nv_bfloat16* __restrict__ hi,
                             __nv_bfloat16* __restrict__ lo, int n4)
{
    const int i = blockIdx.x * blockDim.x + threadIdx.x;
    if (i >= n4) return;
    const float4 v = ((const float4*)src)[i];
    __nv_bfloat16 h0 = __float2bfloat16(v.x);
    __nv_bfloat16 h1 = __float2bfloat16(v.y);
    __nv_bfloat16 h2 = __float2bfloat16(v.z);
    __nv_bfloat16 h3 = __float2bfloat16(v.w);
    __nv_bfloat162 H0; H0.x = h0; H0.y = h1;
    __nv_bfloat162 H1; H1.x = h2; H1.y = h3;
    __nv_bfloat162 L0, L1;
    L0.x = __float2bfloat16(v.x - __bfloat162float(h0));
    L0.y = __float2bfloat16(v.y - __bfloat162float(h1));
    L1.x = __float2bfloat16(v.z - __bfloat162float(h2));
    L1.y = __float2bfloat16(v.w - __bfloat162float(h3));
    ((__nv_bfloat162*)hi)[2 * i]     = H0;
    ((__nv_bfloat162*)hi)[2 * i + 1] = H1;
    ((__nv_bfloat162*)lo)[2 * i]     = L0;
    ((__nv_bfloat162*)lo)[2 * i + 1] = L1;
}

// normalized q rows -> fp32 [h][s][128] + bf16 hi  (one warp per row)
__global__ void qsplit_kernel()
{
    const int gw   = (blockIdx.x * blockDim.x + threadIdx.x) >> 5;
    const int lane = threadIdx.x & 31;
    if (gw >= kNH * kS) return;
    const int h = gw >> 9;
    const int q = gw & 511;
    float4 v = *(const float4*)(g_qkv + (long long)q * kQKVld + h * kD + lane * 4);
    float s = v.x * v.x + v.y * v.y + v.z * v.z + v.w * v.w;
#pragma unroll
    for (int o = 16; o > 0; o >>= 1) s += __shfl_xor_sync(0xffffffffu, s, o);
    const float inv = rsqrtf(s);
    v.x *= inv; v.y *= inv; v.z *= inv; v.w *= inv;
    const long long base = (long long)gw * kD + lane * 4;
    *(float4*)(g_qn_f32 + base) = v;
    __nv_bfloat162 H0, H1;
    H0.x = __float2bfloat16(v.x); H0.y = __float2bfloat16(v.y);
    H1.x = __float2bfloat16(v.z); H1.y = __float2bfloat16(v.w);
    *(__nv_bfloat162*)(g_qn_h + base)     = H0;
    *(__nv_bfloat162*)(g_qn_h + base + 2) = H1;
}

// normalized k_cache rows -> fp32 + bf16 hi  (one warp per row)
__global__ void ksplit_kernel(const float* __restrict__ kc)
{
    const int gw   = (blockIdx.x * blockDim.x + threadIdx.x) >> 5;
    const int lane = threadIdx.x & 31;
    if (gw >= kNH * kSC) return;
    float4 v = *(const float4*)(kc + (long long)gw * kD + lane * 4);
    float s = v.x * v.x + v.y * v.y + v.z * v.z + v.w * v.w;
#pragma unroll
    for (int o = 16; o > 0; o >>= 1) s += __shfl_xor_sync(0xffffffffu, s, o);
    const float inv = rsqrtf(s);
    v.x *= inv; v.y *= inv; v.z *= inv; v.w *= inv;
    const long long base = (long long)gw * kD + lane * 4;
    *(float4*)(g_kn_f32 + base) = v;
    __nv_bfloat162 H0, H1;
    H0.x = __float2bfloat16(v.x); H0.y = __float2bfloat16(v.y);
    H1.x = __float2bfloat16(v.z); H1.y = __float2bfloat16(v.w);
    *(__nv_bfloat162*)(g_kn_h + base)     = H0;
    *(__nv_bfloat162*)(g_kn_h + base + 2) = H1;
}

// ---------------- per-(h,q) approx top-32 over 8192 sims ----------------
__global__ void __launch_bounds__(256)
topk_kernel()
{
    const long long row = blockIdx.x;  // h*512 + q
    const float* sim = g_sim + row * kSC;
    const int tid = threadIdx.x;
    const int lane = tid & 31;
    const int w = tid >> 5;

    float v[32];
#pragma unroll
    for (int i = 0; i < 32; i++) v[i] = sim[tid + (i << 8)];

    __shared__ float wv[8];
    __shared__ int   wi[8];
    __shared__ int   bi;

    for (int r = 0; r < kCand; r++) {
        float mv = -FLT_MAX; int mi = 0x7fffffff;
#pragma unroll
        for (int i = 0; i < 32; i++) {
            if (v[i] > mv) { mv = v[i]; mi = tid + (i << 8); }
        }
#pragma unroll
        for (int o = 16; o > 0; o >>= 1) {
            float ov = __shfl_down_sync(0xffffffffu, mv, o);
            int   oi = __shfl_down_sync(0xffffffffu, mi, o);
            if (ov > mv || (ov == mv && oi < mi)) { mv = ov; mi = oi; }
        }
        if (lane == 0) { wv[w] = mv; wi[w] = mi; }
        __syncthreads();
        if (tid == 0) {
            float m = wv[0]; int ix = wi[0];
#pragma unroll
            for (int k = 1; k < 8; k++)
                if (wv[k] > m || (wv[k] == m && wi[k] < ix)) { m = wv[k]; ix = wi[k]; }
            bi = ix;
            g_cand[row * kCand + r] = ix;
        }
        __syncthreads();
        const int sel = bi;
        if ((sel & 255) == tid) v[sel >> 8] = -FLT_MAX;
    }
}

// ---------------- exact rescore of 32 candidates -> exact top-16 ----------------
// one warp per (h,q) row; normalize-then-dot in fp32 matching reference op order.
__global__ void __launch_bounds__(256)
rescore_kernel()
{
    const int gw   = (blockIdx.x * blockDim.x + threadIdx.x) >> 5;
    const int lane = threadIdx.x & 31;
    if (gw >= kNH * kS) return;
    const int h = gw >> 9;

    const float4 qv = *(const float4*)(g_qn_f32 + (long long)gw * kD + lane * 4);
    int   myidx = g_cand[gw * kCand + lane];
    float myval = -FLT_MAX;

    for (int c = 0; c < kCand; c++) {
        const int idx = __shfl_sync(0xffffffffu, myidx, c);
        const float4 kv = *(const float4*)(g_kn_f32 + ((long long)h * kSC + idx) * kD + lane * 4);
        float p = qv.x * kv.x + qv.y * kv.y + qv.z * kv.z + qv.w * kv.w;
#pragma unroll
        for (int o = 16; o > 0; o >>= 1) p += __shfl_xor_sync(0xffffffffu, p, o);
        if (lane == c) myval = p;
    }

    for (int r = 0; r < kTopK; r++) {
        float v = myval; int ix = myidx;
#pragma unroll
        for (int o = 16; o > 0; o >>= 1) {
            float ov = __shfl_xor_sync(0xffffffffu, v, o);
            int   oi = __shfl_xor_sync(0xffffffffu, ix, o);
            if (ov > v || (ov == v && oi < ix)) { v = ov; ix = oi; }
        }
        if (lane == 0) {
            g_topv[gw * kTopK + r] = v;
            g_topi[gw * kTopK + r] = ix;
        }
        if (myidx == ix) myval = -FLT_MAX;
    }
}

// ---------------- fused attention per (h,q) ----------------
__global__ void __launch_bounds__(256)
attn_kernel(const float* __restrict__ kc, const float* __restrict__ vc,
            const float* __restrict__ bias)
{
    const int q = blockIdx.x;
    const int h = blockIdx.y;
    const int tid = threadIdx.x;
    const int lane = tid & 31;
    const int w = tid >> 5;

    __shared__ float qs[128];
    __shared__ float ssc[16 + kS];
    __shared__ int   sidx[16];
    __shared__ float redw[8];
    __shared__ float bmax, bsuminv;
    __shared__ float ctx2[128];

    const long long rowhq = (long long)h * kS + q;

    if (tid < 128) qs[tid] = g_qkv[(long long)q * kQKVld + h * kD + tid];
    if (tid < 16)  sidx[tid] = g_topi[rowhq * 16 + tid];
    __syncthreads();

    const float4 qv = *(const float4*)(qs + lane * 4);

    for (int j = w; j < 16; j += 8) {
        float s;
        if (g_topv[rowhq * 16 + j] > kSimTh) {
            const float* kp = kc + ((long long)h * kSC + sidx[j]) * kD;
            float4 kv = *(const float4*)(kp + lane * 4);
            float p = qv.x * kv.x + qv.y * kv.y + qv.z * kv.z + qv.w * kv.w;
#pragma unroll
            for (int o = 16; o > 0; o >>= 1) p += __shfl_down_sync(0xffffffffu, p, o);
            s = p * kScale;
        } else {
            s = kNeg;
        }
        if (lane == 0) ssc[j] = s;
    }

    const float* biasrow = bias + ((long long)h * kS + q) * kS;
    for (int kk = w; kk < kS; kk += 8) {
        float s;
        if (kk <= q) {
            const float* kp = g_qkv + (long long)kk * kQKVld + kH + h * kD;
            float4 kv = *(const float4*)(kp + lane * 4);
            float p = qv.x * kv.x + qv.y * kv.y + qv.z * kv.z + qv.w * kv.w;
#pragma unroll
            for (int o = 16; o > 0; o >>= 1) p += __shfl_down_sync(0xffffffffu, p, o);
            s = p * kScale + biasrow[kk];
        } else {
            s = kNeg;
        }
        if (lane == 0) ssc[16 + kk] = s;
    }
    __syncthreads();

    float m = -FLT_MAX;
    for (int j = tid; j < 16 + kS; j += 256) m = fmaxf(m, ssc[j]);
#pragma unroll
    for (int o = 16; o > 0; o >>= 1) m = fmaxf(m, __shfl_down_sync(0xffffffffu, m, o));
    if (lane == 0) redw[w] = m;
    __syncthreads();
    if (tid == 0) {
        float mm = redw[0];
#pragma unroll
        for (int k = 1; k < 8; k++) mm = fmaxf(mm, redw[k]);
        bmax = mm;
    }
    __syncthreads();
    const float msc = bmax;
    float ss = 0.f;
    for (int j = tid; j < 16 + kS; j += 256) {
        float e = __expf(ssc[j] - msc);
        ssc[j] = e;
        ss += e;
    }
#pragma unroll
    for (int o = 16; o > 0; o >>= 1) ss += __shfl_down_sync(0xffffffffu, ss, o);
    if (lane == 0) redw[w] = ss;
    __syncthreads();
    if (tid == 0) {
        float t = 0.f;
#pragma unroll
        for (int k = 0; k < 8; k++) t += redw[k];
        bsuminv = 1.f / t;
    }
    __syncthreads();

    const int g = tid >> 7;
    const int d = tid & 127;
    float acc = 0.f;
    for (int j = g; j < 16; j += 2) {
        float p = ssc[j];
        if (p > 0.f) acc += p * vc[((long long)h * kSC + sidx[j]) * kD + d];
    }
    for (int kk = g; kk <= q; kk += 2) {
        acc += ssc[16 + kk] * g_qkv[(long long)kk * kQKVld + 2 * kH + h * kD + d];
    }
    if (g == 1) ctx2[d] = acc;
    __syncthreads();
    if (g == 0) {
        g_ctx[(long long)q * kH + h * kD + d] = (acc + ctx2[d]) * bsuminv;
    }
}

// ---------------- launcher ----------------
extern "C" void kernel_launch(void* const* d_in, const int* in_sizes, int n_in,
                              void* d_out, int out_size)
{
    const float* hidden = (const float*)d_in[0];
    const float* Wqkv   = (const float*)d_in[1];
    const float* Wout   = (const float*)d_in[2];
    const float* kc     = (const float*)d_in[3];
    const float* vc     = (const float*)d_in[4];
    const float* bias   = (const float*)d_in[5];
    float* out = (float*)d_out;

    float *p_qkv, *p_sim, *p_ctx;
    cudaGetSymbolAddress((void**)&p_qkv,  g_qkv);
    cudaGetSymbolAddress((void**)&p_sim,  g_sim);
    cudaGetSymbolAddress((void**)&p_ctx,  g_ctx);
    __nv_bfloat16 *p_hid_h, *p_hid_l, *p_wqkv_h, *p_wqkv_l, *p_wout_h, *p_wout_l;
    __nv_bfloat16 *p_qn_h, *p_kn_h, *p_ctx_h, *p_ctx_l;
    cudaGetSymbolAddress((void**)&p_hid_h,  g_hid_h);
    cudaGetSymbolAddress((void**)&p_hid_l,  g_hid_l);
    cudaGetSymbolAddress((void**)&p_wqkv_h, g_wqkv_h);
    cudaGetSymbolAddress((void**)&p_wqkv_l, g_wqkv_l);
    cudaGetSymbolAddress((void**)&p_wout_h, g_wout_h);
    cudaGetSymbolAddress((void**)&p_wout_l, g_wout_l);
    cudaGetSymbolAddress((void**)&p_qn_h,   g_qn_h);
    cudaGetSymbolAddress((void**)&p_kn_h,   g_kn_h);
    cudaGetSymbolAddress((void**)&p_ctx_h,  g_ctx_h);
    cudaGetSymbolAddress((void**)&p_ctx_l,  g_ctx_l);

    cudaFuncSetAttribute(mma_gemm<3>, cudaFuncAttributeMaxDynamicSharedMemorySize, 2 * 4 * kMatB);
    cudaFuncSetAttribute(mma_gemm<1>, cudaFuncAttributeMaxDynamicSharedMemorySize, 2 * 2 * kMatB);

    // 1. splits of weights / hidden + normalized k cache (fp32 + bf16)
    split_kernel<<<(kQKVld * kH / 4 + 255) / 256, 256>>>(Wqkv, p_wqkv_h, p_wqkv_l, kQKVld * kH / 4);
    split_kernel<<<(kH * kH / 4 + 255) / 256, 256>>>(Wout, p_wout_h, p_wout_l, kH * kH / 4);
    split_kernel<<<(kS * kH / 4 + 255) / 256, 256>>>(hidden, p_hid_h, p_hid_l, kS * kH / 4);
    ksplit_kernel<<<(kNH * kSC * 32) / 256, 256>>>(kc);

    // 2a. Q projection EXACT fp32: [512,2048] x [2048,2048]^T -> g_qkv cols [0,2048)
    sgemm_nt<<<dim3(kH / 128, kS / 128), 256>>>(hidden, kH, Wqkv, kH, p_qkv, kQKVld, kH);

    // 2b. K,V projections (HMMA 3-prod): [512,2048] x [4096,2048]^T -> g_qkv cols [2048,6144)
    mma_gemm<3><<<dim3(4096 / 128, kS / 128, 1), 256, 2 * 4 * kMatB>>>(
        p_hid_h, p_hid_l, p_wqkv_h + (size_t)2048 * kH, p_wqkv_l + (size_t)2048 * kH,
        p_qkv + 2048, kH, kH, kQKVld, 0, 0, 0, kH);

    // 3. normalized q (fp32 + bf16)
    qsplit_kernel<<<(kNH * kS * 32) / 256, 256>>>();

    // 4. approx cosine-sim GEMM (HMMA 1-prod bf16): per head [512,128]x[8192,128]^T
    mma_gemm<1><<<dim3(kSC / 128, kS / 128, kNH), 256, 2 * 2 * kMatB>>>(
        p_qn_h, nullptr, p_kn_h, nullptr, p_sim,
        kD, kD, kSC,
        (long long)kS * kD, (long long)kSC * kD, (long long)kS * kSC, kD);

    // 5. approx top-32 candidate pool per (h,q)
    topk_kernel<<<kNH * kS, 256>>>();

    // 6. exact fp32 rescore -> exact top-16 values + indices
    rescore_kernel<<<(kNH * kS * 32 + 255) / 256, 256>>>();

    // 7. fused attention -> g_ctx [512, 2048]
    attn_kernel<<<dim3(kS, kNH), 256>>>(kc, vc, bias);

    // 8. ctx split + output projection (HMMA 3-prod)
    split_kernel<<<(kS * kH / 4 + 255) / 256, 256>>>(p_ctx, p_ctx_h, p_ctx_l, kS * kH / 4);
    mma_gemm<3><<<dim3(kH / 128, kS / 128, 1), 256, 2 * 4 * kMatB>>>(
        p_ctx_h, p_ctx_l, p_wout_h, p_wout_l, out,
        kH, kH, kH, 0, 0, 0, kH);
}